// round 5
// baseline (speedup 1.0000x reference)
#include <cuda_runtime.h>
#include <cuda_bf16.h>
#include <math.h>
#include <stdint.h>

// ---------------- constants ----------------
#define DIMC   384
#define HEADS  8
#define HD     48            // head dim
#define NADLA  343           // 7^3 anchors
#define HWD    14
#define NTOK   2744          // 14^3
#define BATCH  8
#define MTOT   (BATCH*NTOK)  // 21952
#define SCALE  0.14433756729740643f  // 48^-0.5

// ---------------- device scratch ----------------
__device__ float g_q   [(long long)MTOT*DIMC];           // 33.7 MB
__device__ float g_kv  [(long long)MTOT*2*DIMC];         // 67.5 MB
__device__ float g_adla[(long long)BATCH*NADLA*DIMC];    // 4.2 MB
__device__ float g_pb  [(long long)HEADS*NADLA*NTOK];    // 30.1 MB
__device__ float g_ab  [(long long)HEADS*NTOK*NADLA];    // 30.1 MB
__device__ float g_logits[(long long)BATCH*HEADS*NADLA*NTOK]; // 241 MB (reused)
__device__ float g_adlav[(long long)BATCH*HEADS*NADLA*HD];    // 4.2 MB
__device__ float g_attn[(long long)MTOT*DIMC];           // 33.7 MB

static inline int cdiv(int a, int b) { return (a + b - 1) / b; }

// ---------------- tf32 helpers ----------------
__device__ __forceinline__ float tf32_rna(float f)
{
    uint32_t r;
    asm("cvt.rna.tf32.f32 %0, %1;" : "=r"(r) : "f"(f));
    return __uint_as_float(r);
}

__device__ __forceinline__ void mma_tf32(float c[4], uint32_t a0, uint32_t a1,
                                         uint32_t a2, uint32_t a3,
                                         uint32_t b0, uint32_t b1)
{
    asm volatile(
        "mma.sync.aligned.m16n8k8.row.col.f32.tf32.tf32.f32 "
        "{%0,%1,%2,%3}, {%4,%5,%6,%7}, {%8,%9}, {%0,%1,%2,%3};"
        : "+f"(c[0]), "+f"(c[1]), "+f"(c[2]), "+f"(c[3])
        : "r"(a0), "r"(a1), "r"(a2), "r"(a3), "r"(b0), "r"(b1));
}

// ---------------- 3xTF32 tensor-core GEMM ----------------
// C[M,N] = alpha * A @ op(B) + bias[col] + Add[row,col]
// BT=false: B row-major [K,N].  BT=true: B row-major [N,K] (i.e. A@B^T).
// Batched over gridDim.z: z -> (b = z>>3, h = z&7) strides.
// Tile: 128x128x16, 256 threads, 8 warps of 64x32.
// Shared layout: hi/lo interleaved pairs, row stride 264 words (conflict-free
// LDS.64 fragment loads: 264 mod 32 == 8).
#define BM 128
#define BN 128
#define ROW 264

template<bool BT>
__global__ void __launch_bounds__(256)
mma_gemm(const float* __restrict__ A, const float* __restrict__ B,
         float* __restrict__ C, const float* __restrict__ bias,
         const float* __restrict__ Add,
         int M, int N, int K, int lda, int ldb, int ldc, int ldadd,
         long long sAb, long long sAh, long long sBb, long long sBh,
         long long sCb, long long sCh, long long sAddh, float alpha)
{
    __shared__ float As[16][ROW];
    __shared__ float Bs[16][ROW];

    int bz = blockIdx.z;
    int bb = bz >> 3, hh = bz & 7;
    A += bb * sAb + hh * sAh;
    B += bb * sBb + hh * sBh;
    C += bb * sCb + hh * sCh;
    if (Add) Add += (long long)hh * sAddh;

    const int tid = threadIdx.x;
    const int warp = tid >> 5, lane = tid & 31;
    const int wm = warp & 1, wn = warp >> 1;          // 2 x 4 warp grid
    const int gid = lane >> 2, ctg = lane & 3;        // mma thread layout
    const int row0 = blockIdx.y * BM, col0 = blockIdx.x * BN;

    const bool alA = (lda & 3) == 0;
    const bool alB = (ldb & 3) == 0;

    float acc[4][4][4];
#pragma unroll
    for (int i = 0; i < 4; i++)
#pragma unroll
        for (int j = 0; j < 4; j++)
#pragma unroll
            for (int t = 0; t < 4; t++) acc[i][j][t] = 0.f;

    for (int k0 = 0; k0 < K; k0 += 16) {
        // ---- stage A: [BM rows] x [16 k], hi/lo pairs, transposed to As[k][2m] ----
#pragma unroll
        for (int i = 0; i < 2; i++) {
            int f = tid + i * 256;
            int r = f >> 2;
            int kq = (f & 3) << 2;
            int gr = row0 + r;
            float v[4] = {0.f, 0.f, 0.f, 0.f};
            if (gr < M) {
                int gk = k0 + kq;
                if (alA && gk + 3 < K) {
                    float4 t = *(const float4*)(A + (long long)gr * lda + gk);
                    v[0] = t.x; v[1] = t.y; v[2] = t.z; v[3] = t.w;
                } else {
#pragma unroll
                    for (int j = 0; j < 4; j++)
                        if (gk + j < K) v[j] = A[(long long)gr * lda + gk + j];
                }
            }
#pragma unroll
            for (int j = 0; j < 4; j++) {
                float hi = tf32_rna(v[j]);
                float lo = tf32_rna(v[j] - hi);
                As[kq + j][2 * r]     = hi;
                As[kq + j][2 * r + 1] = lo;
            }
        }
        // ---- stage B ----
        if (!BT) {
            // B row-major [K,N]: Bs[k][2n] pairs
#pragma unroll
            for (int i = 0; i < 2; i++) {
                int f = tid + i * 256;
                int kk = f >> 5;
                int nq = (f & 31) << 2;
                int gk = k0 + kk;
                float v[4] = {0.f, 0.f, 0.f, 0.f};
                if (gk < K) {
                    int gc = col0 + nq;
                    if (alB && gc + 3 < N) {
                        float4 t = *(const float4*)(B + (long long)gk * ldb + gc);
                        v[0] = t.x; v[1] = t.y; v[2] = t.z; v[3] = t.w;
                    } else {
#pragma unroll
                        for (int j = 0; j < 4; j++)
                            if (gc + j < N) v[j] = B[(long long)gk * ldb + gc + j];
                    }
                }
#pragma unroll
                for (int j = 0; j < 4; j++) {
                    float hi = tf32_rna(v[j]);
                    float lo = tf32_rna(v[j] - hi);
                    Bs[kk][2 * (nq + j)]     = hi;
                    Bs[kk][2 * (nq + j) + 1] = lo;
                }
            }
        } else {
            // B row-major [N,K]: transpose like A
#pragma unroll
            for (int i = 0; i < 2; i++) {
                int f = tid + i * 256;
                int r = f >> 2;
                int kq = (f & 3) << 2;
                int gc = col0 + r;
                float v[4] = {0.f, 0.f, 0.f, 0.f};
                if (gc < N) {
                    int gk = k0 + kq;
                    if (alB && gk + 3 < K) {
                        float4 t = *(const float4*)(B + (long long)gc * ldb + gk);
                        v[0] = t.x; v[1] = t.y; v[2] = t.z; v[3] = t.w;
                    } else {
#pragma unroll
                        for (int j = 0; j < 4; j++)
                            if (gk + j < K) v[j] = B[(long long)gc * ldb + gk + j];
                    }
                }
#pragma unroll
                for (int j = 0; j < 4; j++) {
                    float hi = tf32_rna(v[j]);
                    float lo = tf32_rna(v[j] - hi);
                    Bs[kq + j][2 * r]     = hi;
                    Bs[kq + j][2 * r + 1] = lo;
                }
            }
        }
        __syncthreads();

        // ---- compute: 2 k8 steps ----
#pragma unroll
        for (int k8 = 0; k8 < 2; k8++) {
            int kb = k8 * 8;
            uint32_t Ah[4][4], Al[4][4], Bh[4][2], Bl[4][2];
#pragma unroll
            for (int mt = 0; mt < 4; mt++) {
                int m = wm * 64 + mt * 16 + gid;
                float2 p0 = *(const float2*)&As[kb + ctg][2 * m];
                float2 p1 = *(const float2*)&As[kb + ctg][2 * (m + 8)];
                float2 p2 = *(const float2*)&As[kb + ctg + 4][2 * m];
                float2 p3 = *(const float2*)&As[kb + ctg + 4][2 * (m + 8)];
                Ah[mt][0] = __float_as_uint(p0.x); Al[mt][0] = __float_as_uint(p0.y);
                Ah[mt][1] = __float_as_uint(p1.x); Al[mt][1] = __float_as_uint(p1.y);
                Ah[mt][2] = __float_as_uint(p2.x); Al[mt][2] = __float_as_uint(p2.y);
                Ah[mt][3] = __float_as_uint(p3.x); Al[mt][3] = __float_as_uint(p3.y);
            }
#pragma unroll
            for (int nt = 0; nt < 4; nt++) {
                int n = wn * 32 + nt * 8 + gid;
                float2 q0 = *(const float2*)&Bs[kb + ctg][2 * n];
                float2 q1 = *(const float2*)&Bs[kb + ctg + 4][2 * n];
                Bh[nt][0] = __float_as_uint(q0.x); Bl[nt][0] = __float_as_uint(q0.y);
                Bh[nt][1] = __float_as_uint(q1.x); Bl[nt][1] = __float_as_uint(q1.y);
            }
#pragma unroll
            for (int mt = 0; mt < 4; mt++)
#pragma unroll
                for (int nt = 0; nt < 4; nt++) {
                    // 3xTF32: hi*hi + hi*lo + lo*hi
                    mma_tf32(acc[mt][nt], Ah[mt][0], Ah[mt][1], Ah[mt][2], Ah[mt][3],
                             Bh[nt][0], Bh[nt][1]);
                    mma_tf32(acc[mt][nt], Ah[mt][0], Ah[mt][1], Ah[mt][2], Ah[mt][3],
                             Bl[nt][0], Bl[nt][1]);
                    mma_tf32(acc[mt][nt], Al[mt][0], Al[mt][1], Al[mt][2], Al[mt][3],
                             Bh[nt][0], Bh[nt][1]);
                }
        }
        __syncthreads();
    }

    // ---- epilogue ----
#pragma unroll
    for (int mt = 0; mt < 4; mt++) {
#pragma unroll
        for (int nt = 0; nt < 4; nt++) {
#pragma unroll
            for (int t = 0; t < 4; t++) {
                int gr = row0 + wm * 64 + mt * 16 + gid + ((t >> 1) ? 8 : 0);
                int gc = col0 + wn * 32 + nt * 8 + 2 * ctg + (t & 1);
                if (gr < M && gc < N) {
                    float v = alpha * acc[mt][nt][t];
                    if (bias) v += bias[gc];
                    if (Add)  v += Add[(long long)gr * ldadd + gc];
                    C[(long long)gr * ldc + gc] = v;
                }
            }
        }
    }
}

// ---------------- pooling: adla[b,a,c] = mean of 2x2x2 block of q ----------------
__global__ void pool_adla(const float* __restrict__ q, float* __restrict__ adla)
{
    int idx = blockIdx.x * 256 + threadIdx.x;
    if (idx >= BATCH * NADLA * DIMC) return;
    int c = idx % DIMC;
    int a = (idx / DIMC) % NADLA;
    int b = idx / (DIMC * NADLA);
    int a1 = a / 49, a2 = (a / 7) % 7, a3 = a % 7;
    float s = 0.f;
#pragma unroll
    for (int i = 0; i < 2; i++)
#pragma unroll
        for (int j = 0; j < 2; j++)
#pragma unroll
            for (int k = 0; k < 2; k++) {
                int n = ((2 * a1 + i) * HWD + (2 * a2 + j)) * HWD + (2 * a3 + k);
                s += q[((long long)(b * NTOK + n)) * DIMC + c];
            }
    adla[idx] = s * 0.125f;
}

// linear-interp helper: out index o (0..13) from 7 inputs
__device__ __forceinline__ void lin_w(int o, int& i0, int& i1, float& w)
{
    float x = 0.5f * o - 0.25f;
    x = fminf(fmaxf(x, 0.f), 6.f);
    i0 = (int)floorf(x);
    i1 = min(i0 + 1, 6);
    w = x - (float)i0;
}

__device__ __forceinline__ float interp3(const float* base, int x, int y, int z)
{
    int x0, x1, y0, y1, z0, z1;
    float wx, wy, wz;
    lin_w(x, x0, x1, wx);
    lin_w(y, y0, y1, wy);
    lin_w(z, z0, z1, wz);
    float c000 = base[x0 * 49 + y0 * 7 + z0], c001 = base[x0 * 49 + y0 * 7 + z1];
    float c010 = base[x0 * 49 + y1 * 7 + z0], c011 = base[x0 * 49 + y1 * 7 + z1];
    float c100 = base[x1 * 49 + y0 * 7 + z0], c101 = base[x1 * 49 + y0 * 7 + z1];
    float c110 = base[x1 * 49 + y1 * 7 + z0], c111 = base[x1 * 49 + y1 * 7 + z1];
    float v0 = (1.f - wy) * ((1.f - wz) * c000 + wz * c001) + wy * ((1.f - wz) * c010 + wz * c011);
    float v1 = (1.f - wy) * ((1.f - wz) * c100 + wz * c101) + wy * ((1.f - wz) * c110 + wz * c111);
    return (1.f - wx) * v0 + wx * v1;
}

// pb[h,a,n] = interp(an_bias)[h,a,n] + ah[h,a,x] + aw[h,a,y] + ad[h,a,z]
__global__ void pb_kernel(const float* __restrict__ an, const float* __restrict__ ah,
                          const float* __restrict__ aw, const float* __restrict__ ad,
                          float* __restrict__ pb)
{
    int idx = blockIdx.x * 256 + threadIdx.x;
    if (idx >= HEADS * NADLA * NTOK) return;
    int n = idx % NTOK;
    int a = (idx / NTOK) % NADLA;
    int h = idx / (NTOK * NADLA);
    int x = n / 196, y = (n / 14) % 14, z = n % 14;
    const float* base = an + ((long long)(h * NADLA + a)) * NADLA;
    float v = interp3(base, x, y, z);
    v += ah[(h * NADLA + a) * HWD + x];
    v += aw[(h * NADLA + a) * HWD + y];
    v += ad[(h * NADLA + a) * HWD + z];
    pb[idx] = v;
}

// ab[h,n,a] = interp(na_bias)[h,a,n] + ha[h,x,a] + wa[h,y,a] + da[h,z,a]
__global__ void ab_kernel(const float* __restrict__ na, const float* __restrict__ ha,
                          const float* __restrict__ wa, const float* __restrict__ da,
                          float* __restrict__ ab)
{
    int idx = blockIdx.x * 256 + threadIdx.x;
    if (idx >= HEADS * NTOK * NADLA) return;
    int a = idx % NADLA;
    int n = (idx / NADLA) % NTOK;
    int h = idx / (NADLA * NTOK);
    int x = n / 196, y = (n / 14) % 14, z = n % 14;
    const float* base = na + ((long long)(h * NADLA + a)) * NADLA;
    float v = interp3(base, x, y, z);
    v += ha[(h * HWD + x) * NADLA + a];
    v += wa[(h * HWD + y) * NADLA + a];
    v += da[(h * HWD + z) * NADLA + a];
    ab[idx] = v;
}

// ---------------- softmax over rows ----------------
__device__ __forceinline__ float warpRedMax(float v)
{
#pragma unroll
    for (int o = 16; o; o >>= 1) v = fmaxf(v, __shfl_xor_sync(0xffffffffu, v, o));
    return v;
}
__device__ __forceinline__ float warpRedSum(float v)
{
#pragma unroll
    for (int o = 16; o; o >>= 1) v += __shfl_xor_sync(0xffffffffu, v, o);
    return v;
}

__global__ void softmax_rows(float* __restrict__ data, int len)
{
    extern __shared__ float s[];
    float* red = s + len;
    float* row = data + (long long)blockIdx.x * len;
    int tid = threadIdx.x, nth = blockDim.x;
    int lane = tid & 31, w = tid >> 5, nw = nth >> 5;

    float m = -3.4e38f;
    for (int i = tid; i < len; i += nth) {
        float v = row[i];
        s[i] = v;
        m = fmaxf(m, v);
    }
    m = warpRedMax(m);
    if (lane == 0) red[w] = m;
    __syncthreads();
    m = (lane < nw) ? red[lane] : -3.4e38f;
    m = warpRedMax(m);
    m = __shfl_sync(0xffffffffu, m, 0);
    __syncthreads();

    float sum = 0.f;
    for (int i = tid; i < len; i += nth) {
        float e = __expf(s[i] - m);
        s[i] = e;
        sum += e;
    }
    sum = warpRedSum(sum);
    if (lane == 0) red[w] = sum;
    __syncthreads();
    sum = (lane < nw) ? red[lane] : 0.f;
    sum = warpRedSum(sum);
    sum = __shfl_sync(0xffffffffu, sum, 0);
    float inv = 1.f / sum;
    for (int i = tid; i < len; i += nth) row[i] = s[i] * inv;
}

// ---------------- depthwise 3x3x3 conv on v, added into attn buffer ----------------
__global__ void dwc_add(const float* __restrict__ kv, const float* __restrict__ w,
                        const float* __restrict__ bias, float* __restrict__ attn)
{
    int blk = blockIdx.x; // b*NTOK + n
    int c = threadIdx.x;  // 0..383
    int b = blk / NTOK, n = blk % NTOK;
    int x = n / 196, y = (n / 14) % 14, z = n % 14;
    float acc = bias[c];
    const float* wc = w + c * 27;
#pragma unroll
    for (int i = -1; i <= 1; i++) {
        int xx = x + i;
        if ((unsigned)xx >= (unsigned)HWD) continue;
#pragma unroll
        for (int j = -1; j <= 1; j++) {
            int yy = y + j;
            if ((unsigned)yy >= (unsigned)HWD) continue;
#pragma unroll
            for (int k = -1; k <= 1; k++) {
                int zz = z + k;
                if ((unsigned)zz >= (unsigned)HWD) continue;
                int nn = (xx * HWD + yy) * HWD + zz;
                acc = fmaf(kv[((long long)(b * NTOK + nn)) * 768 + DIMC + c],
                           wc[(i + 1) * 9 + (j + 1) * 3 + (k + 1)], acc);
            }
        }
    }
    attn[(long long)blk * DIMC + c] += acc;
}

// ---------------- launcher ----------------
extern "C" void kernel_launch(void* const* d_in, const int* in_sizes, int n_in,
                              void* d_out, int out_size)
{
    const float* x     = (const float*)d_in[0];
    const float* Wq    = (const float*)d_in[1];
    const float* Wkv   = (const float*)d_in[2];
    const float* Wproj = (const float*)d_in[3];
    const float* bproj = (const float*)d_in[4];
    const float* dwcw  = (const float*)d_in[5];
    const float* dwcb  = (const float*)d_in[6];
    const float* an    = (const float*)d_in[7];
    const float* na    = (const float*)d_in[8];
    const float* ah    = (const float*)d_in[9];
    const float* aw    = (const float*)d_in[10];
    const float* ad    = (const float*)d_in[11];
    const float* ha    = (const float*)d_in[12];
    const float* wa    = (const float*)d_in[13];
    const float* da    = (const float*)d_in[14];
    float* out = (float*)d_out;

    void* p;
    cudaGetSymbolAddress(&p, g_q);      float* q    = (float*)p;
    cudaGetSymbolAddress(&p, g_kv);     float* kv   = (float*)p;
    cudaGetSymbolAddress(&p, g_adla);   float* adla = (float*)p;
    cudaGetSymbolAddress(&p, g_pb);     float* pb   = (float*)p;
    cudaGetSymbolAddress(&p, g_ab);     float* ab   = (float*)p;
    cudaGetSymbolAddress(&p, g_logits); float* lg   = (float*)p;
    cudaGetSymbolAddress(&p, g_adlav);  float* av   = (float*)p;
    cudaGetSymbolAddress(&p, g_attn);   float* at   = (float*)p;

    // 1) q = x @ Wq   (M=21952, N=384, K=384), NN
    mma_gemm<false><<<dim3(cdiv(DIMC, BN), cdiv(MTOT, BM), 1), 256>>>(
        x, Wq, q, nullptr, nullptr,
        MTOT, DIMC, DIMC, DIMC, DIMC, DIMC, 0,
        0, 0, 0, 0, 0, 0, 0, 1.0f);
    // 2) kv = x @ Wkv (N=768), NN
    mma_gemm<false><<<dim3(cdiv(768, BN), cdiv(MTOT, BM), 1), 256>>>(
        x, Wkv, kv, nullptr, nullptr,
        MTOT, 768, DIMC, DIMC, 768, 768, 0,
        0, 0, 0, 0, 0, 0, 0, 1.0f);
    // 3) pooled anchors
    pool_adla<<<cdiv(BATCH * NADLA * DIMC, 256), 256>>>(q, adla);
    // 4) positional bias tables
    pb_kernel<<<cdiv(HEADS * NADLA * NTOK, 256), 256>>>(an, ah, aw, ad, pb);
    ab_kernel<<<cdiv(HEADS * NTOK * NADLA, 256), 256>>>(na, ha, wa, da, ab);

    // 5) logits1[bh, a, n] = SCALE * adla_h @ k_h^T + pb[h]   (NT, M=343, N=2744, K=48)
    mma_gemm<true><<<dim3(cdiv(NTOK, BN), cdiv(NADLA, BM), BATCH * HEADS), 256>>>(
        adla, kv, lg, nullptr, pb,
        NADLA, NTOK, HD, DIMC, 768, NTOK, NTOK,
        (long long)NADLA * DIMC, HD,
        (long long)NTOK * 768, HD,
        (long long)HEADS * NADLA * NTOK, (long long)NADLA * NTOK,
        (long long)NADLA * NTOK, SCALE);
    // 6) softmax over n
    softmax_rows<<<BATCH * HEADS * NADLA, 256, (NTOK + 32) * sizeof(float)>>>(lg, NTOK);
    // 7) adla_v[bh, a, d] = P1 @ v_h   (NN, M=343, N=48, K=2744)
    mma_gemm<false><<<dim3(1, cdiv(NADLA, BM), BATCH * HEADS), 256>>>(
        lg, kv + DIMC, av, nullptr, nullptr,
        NADLA, HD, NTOK, NTOK, 768, HD, 0,
        (long long)HEADS * NADLA * NTOK, (long long)NADLA * NTOK,
        (long long)NTOK * 768, HD,
        (long long)HEADS * NADLA * HD, (long long)NADLA * HD, 0, 1.0f);

    // 8) logits2[bh, n, a] = SCALE * q_h @ adla_h^T + ab[h]   (NT, M=2744, N=343, K=48)
    mma_gemm<true><<<dim3(cdiv(NADLA, BN), cdiv(NTOK, BM), BATCH * HEADS), 256>>>(
        q, adla, lg, nullptr, ab,
        NTOK, NADLA, HD, DIMC, DIMC, NADLA, NADLA,
        (long long)NTOK * DIMC, HD,
        (long long)NADLA * DIMC, HD,
        (long long)HEADS * NTOK * NADLA, (long long)NTOK * NADLA,
        (long long)NTOK * NADLA, SCALE);
    // 9) softmax over a
    softmax_rows<<<BATCH * HEADS * NTOK, 128, (NADLA + 32) * sizeof(float)>>>(lg, NADLA);
    // 10) attn[b, n, h*48+d] = P2 @ adla_v  (NN, M=2744, N=48, K=343; lda=343 -> scalar path)
    mma_gemm<false><<<dim3(1, cdiv(NTOK, BM), BATCH * HEADS), 256>>>(
        lg, av, at, nullptr, nullptr,
        NTOK, HD, NADLA, NADLA, HD, DIMC, 0,
        (long long)HEADS * NTOK * NADLA, (long long)NTOK * NADLA,
        (long long)HEADS * NADLA * HD, (long long)NADLA * HD,
        (long long)NTOK * DIMC, HD, 0, 1.0f);

    // 11) depthwise conv on v, accumulate into attn
    dwc_add<<<BATCH * NTOK, DIMC>>>(kv, dwcw, dwcb, at);

    // 12) out = attn @ Wproj + bproj  (NN)
    mma_gemm<false><<<dim3(cdiv(DIMC, BN), cdiv(MTOT, BM), 1), 256>>>(
        at, Wproj, out, bproj, nullptr,
        MTOT, DIMC, DIMC, DIMC, DIMC, DIMC, 0,
        0, 0, 0, 0, 0, 0, 0, 1.0f);
}

// round 6
// speedup vs baseline: 1.4306x; 1.4306x over previous
#include <cuda_runtime.h>
#include <cuda_bf16.h>
#include <math.h>
#include <stdint.h>
#include <string.h>

#define DIMC   384
#define HEADS  8
#define HD     48
#define NADLA  343
#define HWD    14
#define NTOK   2744
#define BATCH  8
#define MTOT   (BATCH*NTOK)
#define SCALE  0.14433756729740643f

__device__ float g_q   [(long long)MTOT*DIMC];
__device__ float g_kv  [(long long)MTOT*2*DIMC];
__device__ float g_adla[(long long)BATCH*NADLA*DIMC];
__device__ float g_pb  [(long long)HEADS*NADLA*NTOK];
__device__ float g_ab  [(long long)HEADS*NTOK*NADLA];
__device__ float g_adlav[(long long)BATCH*HEADS*NADLA*HD];
__device__ float g_attn[(long long)MTOT*DIMC];

static inline int cdiv(int a, int b) { return (a + b - 1) / b; }

// packed fp32x2 FMA (Blackwell; ptxas never emits it from C++)
__device__ __forceinline__ void fma2(float2& c, float2 a, float2 b)
{
    unsigned long long cc, aa, bb;
    memcpy(&cc, &c, 8); memcpy(&aa, &a, 8); memcpy(&bb, &b, 8);
    asm("fma.rn.f32x2 %0, %1, %2, %0;" : "+l"(cc) : "l"(aa), "l"(bb));
    memcpy(&c, &cc, 8);
}

// ---------------- dense NN sgemm, f32x2 micro-kernel ----------------
// C = A[M,K] @ B[K,N] (+bias). Tile 128x64x16, 256 thr, thread = 8 rows x 4 cols.
__global__ void __launch_bounds__(256)
sgemm_f2(const float* __restrict__ A, const float* __restrict__ B,
         float* __restrict__ C, const float* __restrict__ bias,
         int M, int N, int K)
{
    __shared__ float As[16][132];   // transposed: As[k][m]
    __shared__ float Bs[16][68];

    const int tid = threadIdx.x;
    const int tx = tid & 15, ty = tid >> 4;
    const int row0 = blockIdx.y * 128, col0 = blockIdx.x * 64;

    float2 acc[4][4];
#pragma unroll
    for (int i = 0; i < 4; i++)
#pragma unroll
        for (int j = 0; j < 4; j++) acc[i][j] = make_float2(0.f, 0.f);

    for (int k0 = 0; k0 < K; k0 += 16) {
#pragma unroll
        for (int i = 0; i < 2; i++) {
            int f = tid + i * 256;
            int r = f >> 2, kq = (f & 3) << 2;
            int gr = row0 + r;
            float4 v = make_float4(0.f, 0.f, 0.f, 0.f);
            if (gr < M) v = *(const float4*)(A + (long long)gr * K + k0 + kq);
            As[kq + 0][r] = v.x; As[kq + 1][r] = v.y;
            As[kq + 2][r] = v.z; As[kq + 3][r] = v.w;
        }
        {
            int kk = tid >> 4, nq = (tid & 15) << 2;
            float4 v = *(const float4*)(B + (long long)(k0 + kk) * N + col0 + nq);
            *(float4*)&Bs[kk][nq] = v;
        }
        __syncthreads();
#pragma unroll
        for (int kk = 0; kk < 16; kk++) {
            float2 a2[4];
#pragma unroll
            for (int i = 0; i < 4; i++)
                a2[i] = *(const float2*)&As[kk][ty * 8 + 2 * i];
            float2 b01 = *(const float2*)&Bs[kk][tx * 4];
            float2 b23 = *(const float2*)&Bs[kk][tx * 4 + 2];
            float2 bb[4] = { make_float2(b01.x, b01.x), make_float2(b01.y, b01.y),
                             make_float2(b23.x, b23.x), make_float2(b23.y, b23.y) };
#pragma unroll
            for (int i = 0; i < 4; i++)
#pragma unroll
                for (int j = 0; j < 4; j++) fma2(acc[i][j], a2[i], bb[j]);
        }
        __syncthreads();
    }
#pragma unroll
    for (int i = 0; i < 4; i++) {
        int gr0 = row0 + ty * 8 + 2 * i;
        int gc = col0 + tx * 4;
        float bx[4] = {0, 0, 0, 0};
        if (bias) {
#pragma unroll
            for (int j = 0; j < 4; j++) bx[j] = bias[gc + j];
        }
        if (gr0 < M) {
            float4 o = make_float4(acc[i][0].x + bx[0], acc[i][1].x + bx[1],
                                   acc[i][2].x + bx[2], acc[i][3].x + bx[3]);
            *(float4*)(C + (long long)gr0 * N + gc) = o;
        }
        if (gr0 + 1 < M) {
            float4 o = make_float4(acc[i][0].y + bx[0], acc[i][1].y + bx[1],
                                   acc[i][2].y + bx[2], acc[i][3].y + bx[3]);
            *(float4*)(C + (long long)(gr0 + 1) * N + gc) = o;
        }
    }
}

// ---------------- fused attention 1 (anchors attend to tokens) ----------------
// grid (11, 64), 256 thr. 32 anchors/block, online softmax over 64-token chunks.
#define AT1 32
#define NC1 64
__global__ void __launch_bounds__(256) fused_att1(
    const float* __restrict__ adla, const float* __restrict__ kv,
    const float* __restrict__ pb, float* __restrict__ av)
{
    __shared__ float Ath[AT1][49];
    __shared__ float KsT[48][66];
    __shared__ float Vs[NC1][52];
    __shared__ float Ss[AT1][65];

    const int bh = blockIdx.y, b = bh >> 3, h = bh & 7;
    const int a0 = blockIdx.x * AT1;
    const int tid = threadIdx.x;
    const int aL = tid >> 3, sub = tid & 7;
    const int aG = a0 + aL;
    const int aC = aG < NADLA ? aG : NADLA - 1;
    const int d0 = sub * 6;

    for (int i = tid; i < AT1 * 48; i += 256) {
        int r = i / 48, c = i - r * 48;
        int ag = a0 + r;
        Ath[r][c] = (ag < NADLA)
                  ? adla[((long long)(b * NADLA + ag)) * DIMC + h * HD + c] * SCALE : 0.f;
    }

    const float* pbrow = pb + ((long long)(h * NADLA + aC)) * NTOK;
    float m = -INFINITY, l = 0.f;
    float2 O0 = make_float2(0.f, 0.f), O1 = O0, O2 = O0;
    const int srow = tid >> 2, scol = (tid & 3) * 12;

    for (int c0 = 0; c0 < NTOK; c0 += NC1) {
        {   // stage K^T, V
            int n = c0 + srow;
            bool ok = n < NTOK;
            const float* kb = kv + ((long long)(b * NTOK + (ok ? n : 0))) * 768 + h * HD;
#pragma unroll
            for (int j = 0; j < 12; j += 4) {
                float4 kk = ok ? *(const float4*)(kb + scol + j) : make_float4(0, 0, 0, 0);
                float4 vv = ok ? *(const float4*)(kb + 384 + scol + j) : make_float4(0, 0, 0, 0);
                KsT[scol + j + 0][srow] = kk.x; KsT[scol + j + 1][srow] = kk.y;
                KsT[scol + j + 2][srow] = kk.z; KsT[scol + j + 3][srow] = kk.w;
                *(float4*)&Vs[srow][scol + j] = vv;
            }
        }
        __syncthreads();

        // S = Ath @ K^T, 8 tokens/thread
        float2 acc[4];
#pragma unroll
        for (int j = 0; j < 4; j++) acc[j] = make_float2(0.f, 0.f);
#pragma unroll 8
        for (int d = 0; d < 48; d++) {
            float ad = Ath[aL][d];
            float2 pp = make_float2(ad, ad);
            const float2* krow = (const float2*)&KsT[d][sub * 8];
            fma2(acc[0], pp, krow[0]); fma2(acc[1], pp, krow[1]);
            fma2(acc[2], pp, krow[2]); fma2(acc[3], pp, krow[3]);
        }
        float s[8];
        float mx = -INFINITY;
#pragma unroll
        for (int j = 0; j < 8; j++) {
            int n = c0 + sub * 8 + j;
            float sv = (j & 1) ? acc[j >> 1].y : acc[j >> 1].x;
            s[j] = (n < NTOK) ? sv + pbrow[n] : -INFINITY;
            mx = fmaxf(mx, s[j]);
        }
#pragma unroll
        for (int o = 1; o < 8; o <<= 1)
            mx = fmaxf(mx, __shfl_xor_sync(0xffffffffu, mx, o));
        float mn = fmaxf(m, mx);
        float sum = 0.f;
#pragma unroll
        for (int j = 0; j < 8; j++) {
            float pv = __expf(s[j] - mn);
            Ss[aL][sub * 8 + j] = pv;
            sum += pv;
        }
#pragma unroll
        for (int o = 1; o < 8; o <<= 1)
            sum += __shfl_xor_sync(0xffffffffu, sum, o);
        float fac = __expf(m - mn);
        l = l * fac + sum;
        m = mn;
        O0.x *= fac; O0.y *= fac; O1.x *= fac; O1.y *= fac; O2.x *= fac; O2.y *= fac;
        __syncwarp();

        // O += P @ V (thread: anchor aL, dims d0..d0+5)
#pragma unroll 4
        for (int j = 0; j < NC1; j++) {
            float pv = Ss[aL][j];
            float2 pp = make_float2(pv, pv);
            const float* vr = &Vs[j][d0];
            fma2(O0, pp, *(const float2*)(vr));
            fma2(O1, pp, *(const float2*)(vr + 2));
            fma2(O2, pp, *(const float2*)(vr + 4));
        }
        __syncthreads();
    }

    if (aG < NADLA) {
        float inv = 1.f / l;
        float* dst = av + ((long long)bh * NADLA + aG) * HD + d0;
        dst[0] = O0.x * inv; dst[1] = O0.y * inv;
        dst[2] = O1.x * inv; dst[3] = O1.y * inv;
        dst[4] = O2.x * inv; dst[5] = O2.y * inv;
    }
}

// ---------------- fused attention 2 (tokens attend to anchors), resident ----------------
#define TM2 64
#define ATW 352
#define UNION_WORDS 17836               // max(48*352=16896, 343*52=17836)
#define SM2_BYTES ((UNION_WORDS + TM2*344) * 4)
__global__ void __launch_bounds__(512) fused_att2(
    const float* __restrict__ q, const float* __restrict__ adla,
    const float* __restrict__ av, const float* __restrict__ ab,
    float* __restrict__ attn)
{
    extern __shared__ float sm2[];
    float* AthT = sm2;                  // [48][ATW] during S; then V[343][52]
    float* Ls   = sm2 + UNION_WORDS;    // [64][344]

    const int bh = blockIdx.y, b = bh >> 3, h = bh & 7;
    const int n0 = blockIdx.x * TM2;
    const int tid = threadIdx.x;
    const int r = tid >> 3, t = tid & 7;
    const int n = n0 + r;
    const bool vr = n < NTOK;
    const int nC = vr ? n : NTOK - 1;

    for (int i = tid; i < 48 * ATW; i += 512) {
        int d = i / ATW, a = i - d * ATW;
        AthT[i] = (a < NADLA)
                ? adla[((long long)(b * NADLA + a)) * DIMC + h * HD + d] : 0.f;
    }
    float qreg[48];
    {
        const float* qb = q + ((long long)(b * NTOK + nC)) * DIMC + h * HD;
#pragma unroll
        for (int i = 0; i < 48; i += 4) {
            float4 v = *(const float4*)(qb + i);
            qreg[i] = v.x * SCALE; qreg[i + 1] = v.y * SCALE;
            qreg[i + 2] = v.z * SCALE; qreg[i + 3] = v.w * SCALE;
        }
    }
    __syncthreads();

    // phase A: logits for 44 anchors (packed over anchor pairs)
    const int A0 = t * 44;
    const int ACNT = (A0 + 44 <= NADLA) ? 44 : (NADLA - A0);
    {
        float2 acc[22];
#pragma unroll
        for (int j = 0; j < 22; j++) acc[j] = make_float2(0.f, 0.f);
#pragma unroll 4
        for (int d = 0; d < 48; d++) {
            float qd = qreg[d];
            float2 pp = make_float2(qd, qd);
            const float2* row = (const float2*)&AthT[d * ATW + A0];
#pragma unroll
            for (int j = 0; j < 22; j++) fma2(acc[j], pp, row[j]);
        }
        const float* abrow = ab + ((long long)(h * NTOK + nC)) * NADLA;
#pragma unroll
        for (int j = 0; j < 22; j++) {
            int a = A0 + 2 * j;
            if (a < NADLA)     Ls[r * 344 + a]     = acc[j].x + abrow[a];
            if (a + 1 < NADLA) Ls[r * 344 + a + 1] = acc[j].y + abrow[a + 1];
        }
    }
    __syncwarp();

    // phase B: softmax across 8 threads per row
    float mx = -INFINITY;
    for (int j = 0; j < ACNT; j++) mx = fmaxf(mx, Ls[r * 344 + A0 + j]);
#pragma unroll
    for (int o = 1; o < 8; o <<= 1)
        mx = fmaxf(mx, __shfl_xor_sync(0xffffffffu, mx, o));
    float sum = 0.f;
    for (int j = 0; j < ACNT; j++) {
        float pv = __expf(Ls[r * 344 + A0 + j] - mx);
        Ls[r * 344 + A0 + j] = pv;
        sum += pv;
    }
#pragma unroll
    for (int o = 1; o < 8; o <<= 1)
        sum += __shfl_xor_sync(0xffffffffu, sum, o);
    float inv = 1.f / sum;
    __syncthreads();

    // stage V into union buffer
    float* V = AthT;
    for (int i = tid; i < NADLA * 48; i += 512) {
        int a = i / 48, c = i - a * 48;
        V[a * 52 + c] = av[((long long)bh * NADLA + a) * HD + c];
    }
    __syncthreads();

    // phase C: O = P @ V (thread: row r, dims t*6..+5)
    const int d0 = t * 6;
    float2 O0 = make_float2(0.f, 0.f), O1 = O0, O2 = O0;
    const float* lrow = &Ls[r * 344];
#pragma unroll 4
    for (int a = 0; a < NADLA; a++) {
        float pv = lrow[a];
        float2 pp = make_float2(pv, pv);
        const float* vrow = &V[a * 52 + d0];
        fma2(O0, pp, *(const float2*)(vrow));
        fma2(O1, pp, *(const float2*)(vrow + 2));
        fma2(O2, pp, *(const float2*)(vrow + 4));
    }
    if (vr) {
        float* dst = attn + ((long long)(b * NTOK + n)) * DIMC + h * HD + d0;
        dst[0] = O0.x * inv; dst[1] = O0.y * inv;
        dst[2] = O1.x * inv; dst[3] = O1.y * inv;
        dst[4] = O2.x * inv; dst[5] = O2.y * inv;
    }
}

// ---------------- pooling ----------------
__global__ void pool_adla(const float* __restrict__ q, float* __restrict__ adla)
{
    int idx = blockIdx.x * 256 + threadIdx.x;
    if (idx >= BATCH * NADLA * DIMC) return;
    int c = idx % DIMC;
    int a = (idx / DIMC) % NADLA;
    int b = idx / (DIMC * NADLA);
    int a1 = a / 49, a2 = (a / 7) % 7, a3 = a % 7;
    float s = 0.f;
#pragma unroll
    for (int i = 0; i < 2; i++)
#pragma unroll
        for (int j = 0; j < 2; j++)
#pragma unroll
            for (int k = 0; k < 2; k++) {
                int n = ((2 * a1 + i) * HWD + (2 * a2 + j)) * HWD + (2 * a3 + k);
                s += q[((long long)(b * NTOK + n)) * DIMC + c];
            }
    adla[idx] = s * 0.125f;
}

// ---------------- bias tables ----------------
__device__ __forceinline__ void lin_w(int o, int& i0, int& i1, float& w)
{
    float x = 0.5f * o - 0.25f;
    x = fminf(fmaxf(x, 0.f), 6.f);
    i0 = (int)floorf(x);
    i1 = min(i0 + 1, 6);
    w = x - (float)i0;
}

__device__ __forceinline__ float interp3(const float* base, int x, int y, int z)
{
    int x0, x1, y0, y1, z0, z1;
    float wx, wy, wz;
    lin_w(x, x0, x1, wx); lin_w(y, y0, y1, wy); lin_w(z, z0, z1, wz);
    float c000 = base[x0 * 49 + y0 * 7 + z0], c001 = base[x0 * 49 + y0 * 7 + z1];
    float c010 = base[x0 * 49 + y1 * 7 + z0], c011 = base[x0 * 49 + y1 * 7 + z1];
    float c100 = base[x1 * 49 + y0 * 7 + z0], c101 = base[x1 * 49 + y0 * 7 + z1];
    float c110 = base[x1 * 49 + y1 * 7 + z0], c111 = base[x1 * 49 + y1 * 7 + z1];
    float v0 = (1.f - wy) * ((1.f - wz) * c000 + wz * c001) + wy * ((1.f - wz) * c010 + wz * c011);
    float v1 = (1.f - wy) * ((1.f - wz) * c100 + wz * c101) + wy * ((1.f - wz) * c110 + wz * c111);
    return (1.f - wx) * v0 + wx * v1;
}

__global__ void pb_kernel(const float* __restrict__ an, const float* __restrict__ ah,
                          const float* __restrict__ aw, const float* __restrict__ ad,
                          float* __restrict__ pb)
{
    int idx = blockIdx.x * 256 + threadIdx.x;
    if (idx >= HEADS * NADLA * NTOK) return;
    int n = idx % NTOK;
    int a = (idx / NTOK) % NADLA;
    int h = idx / (NTOK * NADLA);
    int x = n / 196, y = (n / 14) % 14, z = n % 14;
    const float* base = an + ((long long)(h * NADLA + a)) * NADLA;
    float v = interp3(base, x, y, z);
    v += ah[(h * NADLA + a) * HWD + x];
    v += aw[(h * NADLA + a) * HWD + y];
    v += ad[(h * NADLA + a) * HWD + z];
    pb[idx] = v;
}

__global__ void ab_kernel(const float* __restrict__ na, const float* __restrict__ ha,
                          const float* __restrict__ wa, const float* __restrict__ da,
                          float* __restrict__ ab)
{
    int idx = blockIdx.x * 256 + threadIdx.x;
    if (idx >= HEADS * NTOK * NADLA) return;
    int a = idx % NADLA;
    int n = (idx / NADLA) % NTOK;
    int h = idx / (NADLA * NTOK);
    int x = n / 196, y = (n / 14) % 14, z = n % 14;
    const float* base = na + ((long long)(h * NADLA + a)) * NADLA;
    float v = interp3(base, x, y, z);
    v += ha[(h * HWD + x) * NADLA + a];
    v += wa[(h * HWD + y) * NADLA + a];
    v += da[(h * HWD + z) * NADLA + a];
    ab[idx] = v;
}

// ---------------- depthwise 3x3x3 conv, += into attn ----------------
__global__ void dwc_add(const float* __restrict__ kv, const float* __restrict__ w,
                        const float* __restrict__ bias, float* __restrict__ attn)
{
    int blk = blockIdx.x;
    int c = threadIdx.x;
    int b = blk / NTOK, n = blk % NTOK;
    int x = n / 196, y = (n / 14) % 14, z = n % 14;
    float acc = bias[c];
    const float* wc = w + c * 27;
#pragma unroll
    for (int i = -1; i <= 1; i++) {
        int xx = x + i;
        if ((unsigned)xx >= (unsigned)HWD) continue;
#pragma unroll
        for (int j = -1; j <= 1; j++) {
            int yy = y + j;
            if ((unsigned)yy >= (unsigned)HWD) continue;
#pragma unroll
            for (int k = -1; k <= 1; k++) {
                int zz = z + k;
                if ((unsigned)zz >= (unsigned)HWD) continue;
                int nn = (xx * HWD + yy) * HWD + zz;
                acc = fmaf(kv[((long long)(b * NTOK + nn)) * 768 + DIMC + c],
                           wc[(i + 1) * 9 + (j + 1) * 3 + (k + 1)], acc);
            }
        }
    }
    attn[(long long)blk * DIMC + c] += acc;
}

// ---------------- launcher ----------------
extern "C" void kernel_launch(void* const* d_in, const int* in_sizes, int n_in,
                              void* d_out, int out_size)
{
    const float* x     = (const float*)d_in[0];
    const float* Wq    = (const float*)d_in[1];
    const float* Wkv   = (const float*)d_in[2];
    const float* Wproj = (const float*)d_in[3];
    const float* bproj = (const float*)d_in[4];
    const float* dwcw  = (const float*)d_in[5];
    const float* dwcb  = (const float*)d_in[6];
    const float* an    = (const float*)d_in[7];
    const float* na    = (const float*)d_in[8];
    const float* ah    = (const float*)d_in[9];
    const float* aw    = (const float*)d_in[10];
    const float* ad    = (const float*)d_in[11];
    const float* ha    = (const float*)d_in[12];
    const float* wa    = (const float*)d_in[13];
    const float* da    = (const float*)d_in[14];
    float* out = (float*)d_out;

    void* p;
    cudaGetSymbolAddress(&p, g_q);     float* q    = (float*)p;
    cudaGetSymbolAddress(&p, g_kv);    float* kv   = (float*)p;
    cudaGetSymbolAddress(&p, g_adla);  float* adla = (float*)p;
    cudaGetSymbolAddress(&p, g_pb);    float* pb   = (float*)p;
    cudaGetSymbolAddress(&p, g_ab);    float* ab   = (float*)p;
    cudaGetSymbolAddress(&p, g_adlav); float* av   = (float*)p;
    cudaGetSymbolAddress(&p, g_attn);  float* at   = (float*)p;

    static bool attr_done = false;
    if (!attr_done) {
        cudaFuncSetAttribute(fused_att2, cudaFuncAttributeMaxDynamicSharedMemorySize,
                             SM2_BYTES);
        attr_done = true;
    }

    // 1) q = x @ Wq
    sgemm_f2<<<dim3(DIMC / 64, cdiv(MTOT, 128)), 256>>>(x, Wq, q, nullptr, MTOT, DIMC, DIMC);
    // 2) kv = x @ Wkv
    sgemm_f2<<<dim3(768 / 64, cdiv(MTOT, 128)), 256>>>(x, Wkv, kv, nullptr, MTOT, 768, DIMC);
    // 3) pooled anchors
    pool_adla<<<cdiv(BATCH * NADLA * DIMC, 256), 256>>>(q, adla);
    // 4) bias tables
    pb_kernel<<<cdiv(HEADS * NADLA * NTOK, 256), 256>>>(an, ah, aw, ad, pb);
    ab_kernel<<<cdiv(HEADS * NTOK * NADLA, 256), 256>>>(na, ha, wa, da, ab);
    // 5) fused attention 1 -> adla_v
    fused_att1<<<dim3(cdiv(NADLA, AT1), BATCH * HEADS), 256>>>(adla, kv, pb, av);
    // 6) fused attention 2 -> attn
    fused_att2<<<dim3(cdiv(NTOK, TM2), BATCH * HEADS), 512, SM2_BYTES>>>(q, adla, av, ab, at);
    // 7) depthwise conv += attn
    dwc_add<<<BATCH * NTOK, DIMC>>>(kv, dwcw, dwcb, at);
    // 8) out = attn @ Wproj + bproj
    sgemm_f2<<<dim3(DIMC / 64, cdiv(MTOT, 128)), 256>>>(at, Wproj, out, bproj, MTOT, DIMC, DIMC);
}

// round 7
// speedup vs baseline: 1.4337x; 1.0022x over previous
#include <cuda_runtime.h>
#include <cuda_bf16.h>
#include <math.h>
#include <stdint.h>
#include <string.h>

#define DIMC   384
#define HEADS  8
#define HD     48
#define NADLA  343
#define HWD    14
#define NTOK   2744
#define BATCH  8
#define MTOT   (BATCH*NTOK)
#define SCALE  0.14433756729740643f

__device__ float g_q   [(long long)MTOT*DIMC];
__device__ float g_kv  [(long long)MTOT*2*DIMC];
__device__ float g_adla[(long long)BATCH*NADLA*DIMC];
__device__ float g_pb  [(long long)HEADS*NADLA*NTOK];
__device__ float g_ab  [(long long)HEADS*NTOK*NADLA];
__device__ float g_adlav[(long long)BATCH*HEADS*NADLA*HD];
__device__ float g_attn[(long long)MTOT*DIMC];

static inline int cdiv(int a, int b) { return (a + b - 1) / b; }

// packed fp32x2 FMA (Blackwell; ptxas never emits it from C++)
__device__ __forceinline__ void fma2(float2& c, float2 a, float2 b)
{
    unsigned long long cc, aa, bb;
    memcpy(&cc, &c, 8); memcpy(&aa, &a, 8); memcpy(&bb, &b, 8);
    asm("fma.rn.f32x2 %0, %1, %2, %0;" : "+l"(cc) : "l"(aa), "l"(bb));
    memcpy(&c, &cc, 8);
}

// ---------------- dense NN sgemm, f32x2 micro-kernel ----------------
// C = A[M,K] @ B[K,N] (+bias). Tile 128x64x16, 256 thr, thread = 8 rows x 4 cols.
__global__ void __launch_bounds__(256)
sgemm_f2(const float* __restrict__ A, const float* __restrict__ B,
         float* __restrict__ C, const float* __restrict__ bias,
         int M, int N, int K)
{
    __shared__ float As[16][132];   // transposed: As[k][m]
    __shared__ float Bs[16][68];

    const int tid = threadIdx.x;
    const int tx = tid & 15, ty = tid >> 4;
    const int row0 = blockIdx.y * 128, col0 = blockIdx.x * 64;

    float2 acc[4][4];
#pragma unroll
    for (int i = 0; i < 4; i++)
#pragma unroll
        for (int j = 0; j < 4; j++) acc[i][j] = make_float2(0.f, 0.f);

    for (int k0 = 0; k0 < K; k0 += 16) {
#pragma unroll
        for (int i = 0; i < 2; i++) {
            int f = tid + i * 256;
            int r = f >> 2, kq = (f & 3) << 2;
            int gr = row0 + r;
            float4 v = make_float4(0.f, 0.f, 0.f, 0.f);
            if (gr < M) v = *(const float4*)(A + (long long)gr * K + k0 + kq);
            As[kq + 0][r] = v.x; As[kq + 1][r] = v.y;
            As[kq + 2][r] = v.z; As[kq + 3][r] = v.w;
        }
        {
            int kk = tid >> 4, nq = (tid & 15) << 2;
            float4 v = *(const float4*)(B + (long long)(k0 + kk) * N + col0 + nq);
            *(float4*)&Bs[kk][nq] = v;
        }
        __syncthreads();
#pragma unroll
        for (int kk = 0; kk < 16; kk++) {
            float2 a2[4];
#pragma unroll
            for (int i = 0; i < 4; i++)
                a2[i] = *(const float2*)&As[kk][ty * 8 + 2 * i];
            float2 b01 = *(const float2*)&Bs[kk][tx * 4];
            float2 b23 = *(const float2*)&Bs[kk][tx * 4 + 2];
            float2 bb[4] = { make_float2(b01.x, b01.x), make_float2(b01.y, b01.y),
                             make_float2(b23.x, b23.x), make_float2(b23.y, b23.y) };
#pragma unroll
            for (int i = 0; i < 4; i++)
#pragma unroll
                for (int j = 0; j < 4; j++) fma2(acc[i][j], a2[i], bb[j]);
        }
        __syncthreads();
    }
#pragma unroll
    for (int i = 0; i < 4; i++) {
        int gr0 = row0 + ty * 8 + 2 * i;
        int gc = col0 + tx * 4;
        float bx[4] = {0, 0, 0, 0};
        if (bias) {
#pragma unroll
            for (int j = 0; j < 4; j++) bx[j] = bias[gc + j];
        }
        if (gr0 < M) {
            float4 o = make_float4(acc[i][0].x + bx[0], acc[i][1].x + bx[1],
                                   acc[i][2].x + bx[2], acc[i][3].x + bx[3]);
            *(float4*)(C + (long long)gr0 * N + gc) = o;
        }
        if (gr0 + 1 < M) {
            float4 o = make_float4(acc[i][0].y + bx[0], acc[i][1].y + bx[1],
                                   acc[i][2].y + bx[2], acc[i][3].y + bx[3]);
            *(float4*)(C + (long long)(gr0 + 1) * N + gc) = o;
        }
    }
}

// ---------------- fused attention 1 (anchors attend to tokens) ----------------
// grid (11, 64), 256 thr. 32 anchors/block, online softmax over 64-token chunks.
#define AT1 32
#define NC1 64
__global__ void __launch_bounds__(256) fused_att1(
    const float* __restrict__ adla, const float* __restrict__ kv,
    const float* __restrict__ pb, float* __restrict__ av)
{
    __shared__ float Ath[AT1][49];
    __shared__ float KsT[48][66];
    __shared__ float Vs[NC1][52];
    __shared__ float Ss[AT1][65];

    const int bh = blockIdx.y, b = bh >> 3, h = bh & 7;
    const int a0 = blockIdx.x * AT1;
    const int tid = threadIdx.x;
    const int aL = tid >> 3, sub = tid & 7;
    const int aG = a0 + aL;
    const int aC = aG < NADLA ? aG : NADLA - 1;
    const int d0 = sub * 6;

    for (int i = tid; i < AT1 * 48; i += 256) {
        int r = i / 48, c = i - r * 48;
        int ag = a0 + r;
        Ath[r][c] = (ag < NADLA)
                  ? adla[((long long)(b * NADLA + ag)) * DIMC + h * HD + c] * SCALE : 0.f;
    }

    const float* pbrow = pb + ((long long)(h * NADLA + aC)) * NTOK;
    float m = -INFINITY, l = 0.f;
    float2 O0 = make_float2(0.f, 0.f), O1 = O0, O2 = O0;
    const int srow = tid >> 2, scol = (tid & 3) * 12;

    for (int c0 = 0; c0 < NTOK; c0 += NC1) {
        {   // stage K^T, V
            int n = c0 + srow;
            bool ok = n < NTOK;
            const float* kb = kv + ((long long)(b * NTOK + (ok ? n : 0))) * 768 + h * HD;
#pragma unroll
            for (int j = 0; j < 12; j += 4) {
                float4 kk = ok ? *(const float4*)(kb + scol + j) : make_float4(0, 0, 0, 0);
                float4 vv = ok ? *(const float4*)(kb + 384 + scol + j) : make_float4(0, 0, 0, 0);
                KsT[scol + j + 0][srow] = kk.x; KsT[scol + j + 1][srow] = kk.y;
                KsT[scol + j + 2][srow] = kk.z; KsT[scol + j + 3][srow] = kk.w;
                *(float4*)&Vs[srow][scol + j] = vv;
            }
        }
        __syncthreads();

        // S = Ath @ K^T, 8 tokens/thread
        float2 acc[4];
#pragma unroll
        for (int j = 0; j < 4; j++) acc[j] = make_float2(0.f, 0.f);
#pragma unroll 8
        for (int d = 0; d < 48; d++) {
            float ad = Ath[aL][d];
            float2 pp = make_float2(ad, ad);
            const float2* krow = (const float2*)&KsT[d][sub * 8];
            fma2(acc[0], pp, krow[0]); fma2(acc[1], pp, krow[1]);
            fma2(acc[2], pp, krow[2]); fma2(acc[3], pp, krow[3]);
        }
        float s[8];
        float mx = -INFINITY;
#pragma unroll
        for (int j = 0; j < 8; j++) {
            int n = c0 + sub * 8 + j;
            float sv = (j & 1) ? acc[j >> 1].y : acc[j >> 1].x;
            s[j] = (n < NTOK) ? sv + pbrow[n] : -INFINITY;
            mx = fmaxf(mx, s[j]);
        }
#pragma unroll
        for (int o = 1; o < 8; o <<= 1)
            mx = fmaxf(mx, __shfl_xor_sync(0xffffffffu, mx, o));
        float mn = fmaxf(m, mx);
        float sum = 0.f;
#pragma unroll
        for (int j = 0; j < 8; j++) {
            float pv = __expf(s[j] - mn);
            Ss[aL][sub * 8 + j] = pv;
            sum += pv;
        }
#pragma unroll
        for (int o = 1; o < 8; o <<= 1)
            sum += __shfl_xor_sync(0xffffffffu, sum, o);
        float fac = __expf(m - mn);
        l = l * fac + sum;
        m = mn;
        O0.x *= fac; O0.y *= fac; O1.x *= fac; O1.y *= fac; O2.x *= fac; O2.y *= fac;
        __syncwarp();

        // O += P @ V (thread: anchor aL, dims d0..d0+5)
#pragma unroll 4
        for (int j = 0; j < NC1; j++) {
            float pv = Ss[aL][j];
            float2 pp = make_float2(pv, pv);
            const float* vr = &Vs[j][d0];
            fma2(O0, pp, *(const float2*)(vr));
            fma2(O1, pp, *(const float2*)(vr + 2));
            fma2(O2, pp, *(const float2*)(vr + 4));
        }
        __syncthreads();
    }

    if (aG < NADLA) {
        float inv = 1.f / l;
        float* dst = av + ((long long)bh * NADLA + aG) * HD + d0;
        dst[0] = O0.x * inv; dst[1] = O0.y * inv;
        dst[2] = O1.x * inv; dst[3] = O1.y * inv;
        dst[4] = O2.x * inv; dst[5] = O2.y * inv;
    }
}

// ---------------- fused attention 2 (tokens attend to anchors), resident ----------------
#define TM2 64
#define ATW 352
#define UNION_WORDS 17836               // max(48*352=16896, 343*52=17836)
#define SM2_BYTES ((UNION_WORDS + TM2*344) * 4)
__global__ void __launch_bounds__(512) fused_att2(
    const float* __restrict__ q, const float* __restrict__ adla,
    const float* __restrict__ av, const float* __restrict__ ab,
    float* __restrict__ attn)
{
    extern __shared__ float sm2[];
    float* AthT = sm2;                  // [48][ATW] during S; then V[343][52]
    float* Ls   = sm2 + UNION_WORDS;    // [64][344]

    const int bh = blockIdx.y, b = bh >> 3, h = bh & 7;
    const int n0 = blockIdx.x * TM2;
    const int tid = threadIdx.x;
    const int r = tid >> 3, t = tid & 7;
    const int n = n0 + r;
    const bool vr = n < NTOK;
    const int nC = vr ? n : NTOK - 1;

    for (int i = tid; i < 48 * ATW; i += 512) {
        int d = i / ATW, a = i - d * ATW;
        AthT[i] = (a < NADLA)
                ? adla[((long long)(b * NADLA + a)) * DIMC + h * HD + d] : 0.f;
    }
    float qreg[48];
    {
        const float* qb = q + ((long long)(b * NTOK + nC)) * DIMC + h * HD;
#pragma unroll
        for (int i = 0; i < 48; i += 4) {
            float4 v = *(const float4*)(qb + i);
            qreg[i] = v.x * SCALE; qreg[i + 1] = v.y * SCALE;
            qreg[i + 2] = v.z * SCALE; qreg[i + 3] = v.w * SCALE;
        }
    }
    __syncthreads();

    // phase A: logits for 44 anchors (packed over anchor pairs)
    const int A0 = t * 44;
    const int ACNT = (A0 + 44 <= NADLA) ? 44 : (NADLA - A0);
    {
        float2 acc[22];
#pragma unroll
        for (int j = 0; j < 22; j++) acc[j] = make_float2(0.f, 0.f);
#pragma unroll 4
        for (int d = 0; d < 48; d++) {
            float qd = qreg[d];
            float2 pp = make_float2(qd, qd);
            const float2* row = (const float2*)&AthT[d * ATW + A0];
#pragma unroll
            for (int j = 0; j < 22; j++) fma2(acc[j], pp, row[j]);
        }
        const float* abrow = ab + ((long long)(h * NTOK + nC)) * NADLA;
#pragma unroll
        for (int j = 0; j < 22; j++) {
            int a = A0 + 2 * j;
            if (a < NADLA)     Ls[r * 344 + a]     = acc[j].x + abrow[a];
            if (a + 1 < NADLA) Ls[r * 344 + a + 1] = acc[j].y + abrow[a + 1];
        }
    }
    __syncwarp();

    // phase B: softmax across 8 threads per row
    float mx = -INFINITY;
    for (int j = 0; j < ACNT; j++) mx = fmaxf(mx, Ls[r * 344 + A0 + j]);
#pragma unroll
    for (int o = 1; o < 8; o <<= 1)
        mx = fmaxf(mx, __shfl_xor_sync(0xffffffffu, mx, o));
    float sum = 0.f;
    for (int j = 0; j < ACNT; j++) {
        float pv = __expf(Ls[r * 344 + A0 + j] - mx);
        Ls[r * 344 + A0 + j] = pv;
        sum += pv;
    }
#pragma unroll
    for (int o = 1; o < 8; o <<= 1)
        sum += __shfl_xor_sync(0xffffffffu, sum, o);
    float inv = 1.f / sum;
    __syncthreads();

    // stage V into union buffer
    float* V = AthT;
    for (int i = tid; i < NADLA * 48; i += 512) {
        int a = i / 48, c = i - a * 48;
        V[a * 52 + c] = av[((long long)bh * NADLA + a) * HD + c];
    }
    __syncthreads();

    // phase C: O = P @ V (thread: row r, dims t*6..+5)
    const int d0 = t * 6;
    float2 O0 = make_float2(0.f, 0.f), O1 = O0, O2 = O0;
    const float* lrow = &Ls[r * 344];
#pragma unroll 4
    for (int a = 0; a < NADLA; a++) {
        float pv = lrow[a];
        float2 pp = make_float2(pv, pv);
        const float* vrow = &V[a * 52 + d0];
        fma2(O0, pp, *(const float2*)(vrow));
        fma2(O1, pp, *(const float2*)(vrow + 2));
        fma2(O2, pp, *(const float2*)(vrow + 4));
    }
    if (vr) {
        float* dst = attn + ((long long)(b * NTOK + n)) * DIMC + h * HD + d0;
        dst[0] = O0.x * inv; dst[1] = O0.y * inv;
        dst[2] = O1.x * inv; dst[3] = O1.y * inv;
        dst[4] = O2.x * inv; dst[5] = O2.y * inv;
    }
}

// ---------------- pooling ----------------
__global__ void pool_adla(const float* __restrict__ q, float* __restrict__ adla)
{
    int idx = blockIdx.x * 256 + threadIdx.x;
    if (idx >= BATCH * NADLA * DIMC) return;
    int c = idx % DIMC;
    int a = (idx / DIMC) % NADLA;
    int b = idx / (DIMC * NADLA);
    int a1 = a / 49, a2 = (a / 7) % 7, a3 = a % 7;
    float s = 0.f;
#pragma unroll
    for (int i = 0; i < 2; i++)
#pragma unroll
        for (int j = 0; j < 2; j++)
#pragma unroll
            for (int k = 0; k < 2; k++) {
                int n = ((2 * a1 + i) * HWD + (2 * a2 + j)) * HWD + (2 * a3 + k);
                s += q[((long long)(b * NTOK + n)) * DIMC + c];
            }
    adla[idx] = s * 0.125f;
}

// ---------------- bias tables ----------------
__device__ __forceinline__ void lin_w(int o, int& i0, int& i1, float& w)
{
    float x = 0.5f * o - 0.25f;
    x = fminf(fmaxf(x, 0.f), 6.f);
    i0 = (int)floorf(x);
    i1 = min(i0 + 1, 6);
    w = x - (float)i0;
}

__device__ __forceinline__ float interp3(const float* base, int x, int y, int z)
{
    int x0, x1, y0, y1, z0, z1;
    float wx, wy, wz;
    lin_w(x, x0, x1, wx); lin_w(y, y0, y1, wy); lin_w(z, z0, z1, wz);
    float c000 = base[x0 * 49 + y0 * 7 + z0], c001 = base[x0 * 49 + y0 * 7 + z1];
    float c010 = base[x0 * 49 + y1 * 7 + z0], c011 = base[x0 * 49 + y1 * 7 + z1];
    float c100 = base[x1 * 49 + y0 * 7 + z0], c101 = base[x1 * 49 + y0 * 7 + z1];
    float c110 = base[x1 * 49 + y1 * 7 + z0], c111 = base[x1 * 49 + y1 * 7 + z1];
    float v0 = (1.f - wy) * ((1.f - wz) * c000 + wz * c001) + wy * ((1.f - wz) * c010 + wz * c011);
    float v1 = (1.f - wy) * ((1.f - wz) * c100 + wz * c101) + wy * ((1.f - wz) * c110 + wz * c111);
    return (1.f - wx) * v0 + wx * v1;
}

__global__ void pb_kernel(const float* __restrict__ an, const float* __restrict__ ah,
                          const float* __restrict__ aw, const float* __restrict__ ad,
                          float* __restrict__ pb)
{
    int idx = blockIdx.x * 256 + threadIdx.x;
    if (idx >= HEADS * NADLA * NTOK) return;
    int n = idx % NTOK;
    int a = (idx / NTOK) % NADLA;
    int h = idx / (NTOK * NADLA);
    int x = n / 196, y = (n / 14) % 14, z = n % 14;
    const float* base = an + ((long long)(h * NADLA + a)) * NADLA;
    float v = interp3(base, x, y, z);
    v += ah[(h * NADLA + a) * HWD + x];
    v += aw[(h * NADLA + a) * HWD + y];
    v += ad[(h * NADLA + a) * HWD + z];
    pb[idx] = v;
}

__global__ void ab_kernel(const float* __restrict__ na, const float* __restrict__ ha,
                          const float* __restrict__ wa, const float* __restrict__ da,
                          float* __restrict__ ab)
{
    int idx = blockIdx.x * 256 + threadIdx.x;
    if (idx >= HEADS * NTOK * NADLA) return;
    int a = idx % NADLA;
    int n = (idx / NADLA) % NTOK;
    int h = idx / (NADLA * NTOK);
    int x = n / 196, y = (n / 14) % 14, z = n % 14;
    const float* base = na + ((long long)(h * NADLA + a)) * NADLA;
    float v = interp3(base, x, y, z);
    v += ha[(h * HWD + x) * NADLA + a];
    v += wa[(h * HWD + y) * NADLA + a];
    v += da[(h * HWD + z) * NADLA + a];
    ab[idx] = v;
}

// ---------------- depthwise 3x3x3 conv, += into attn ----------------
__global__ void dwc_add(const float* __restrict__ kv, const float* __restrict__ w,
                        const float* __restrict__ bias, float* __restrict__ attn)
{
    int blk = blockIdx.x;
    int c = threadIdx.x;
    int b = blk / NTOK, n = blk % NTOK;
    int x = n / 196, y = (n / 14) % 14, z = n % 14;
    float acc = bias[c];
    const float* wc = w + c * 27;
#pragma unroll
    for (int i = -1; i <= 1; i++) {
        int xx = x + i;
        if ((unsigned)xx >= (unsigned)HWD) continue;
#pragma unroll
        for (int j = -1; j <= 1; j++) {
            int yy = y + j;
            if ((unsigned)yy >= (unsigned)HWD) continue;
#pragma unroll
            for (int k = -1; k <= 1; k++) {
                int zz = z + k;
                if ((unsigned)zz >= (unsigned)HWD) continue;
                int nn = (xx * HWD + yy) * HWD + zz;
                acc = fmaf(kv[((long long)(b * NTOK + nn)) * 768 + DIMC + c],
                           wc[(i + 1) * 9 + (j + 1) * 3 + (k + 1)], acc);
            }
        }
    }
    attn[(long long)blk * DIMC + c] += acc;
}

// ---------------- launcher ----------------
extern "C" void kernel_launch(void* const* d_in, const int* in_sizes, int n_in,
                              void* d_out, int out_size)
{
    const float* x     = (const float*)d_in[0];
    const float* Wq    = (const float*)d_in[1];
    const float* Wkv   = (const float*)d_in[2];
    const float* Wproj = (const float*)d_in[3];
    const float* bproj = (const float*)d_in[4];
    const float* dwcw  = (const float*)d_in[5];
    const float* dwcb  = (const float*)d_in[6];
    const float* an    = (const float*)d_in[7];
    const float* na    = (const float*)d_in[8];
    const float* ah    = (const float*)d_in[9];
    const float* aw    = (const float*)d_in[10];
    const float* ad    = (const float*)d_in[11];
    const float* ha    = (const float*)d_in[12];
    const float* wa    = (const float*)d_in[13];
    const float* da    = (const float*)d_in[14];
    float* out = (float*)d_out;

    void* p;
    cudaGetSymbolAddress(&p, g_q);     float* q    = (float*)p;
    cudaGetSymbolAddress(&p, g_kv);    float* kv   = (float*)p;
    cudaGetSymbolAddress(&p, g_adla);  float* adla = (float*)p;
    cudaGetSymbolAddress(&p, g_pb);    float* pb   = (float*)p;
    cudaGetSymbolAddress(&p, g_ab);    float* ab   = (float*)p;
    cudaGetSymbolAddress(&p, g_adlav); float* av   = (float*)p;
    cudaGetSymbolAddress(&p, g_attn);  float* at   = (float*)p;

    static bool attr_done = false;
    if (!attr_done) {
        cudaFuncSetAttribute(fused_att2, cudaFuncAttributeMaxDynamicSharedMemorySize,
                             SM2_BYTES);
        attr_done = true;
    }

    // 1) q = x @ Wq
    sgemm_f2<<<dim3(DIMC / 64, cdiv(MTOT, 128)), 256>>>(x, Wq, q, nullptr, MTOT, DIMC, DIMC);
    // 2) kv = x @ Wkv
    sgemm_f2<<<dim3(768 / 64, cdiv(MTOT, 128)), 256>>>(x, Wkv, kv, nullptr, MTOT, 768, DIMC);
    // 3) pooled anchors
    pool_adla<<<cdiv(BATCH * NADLA * DIMC, 256), 256>>>(q, adla);
    // 4) bias tables
    pb_kernel<<<cdiv(HEADS * NADLA * NTOK, 256), 256>>>(an, ah, aw, ad, pb);
    ab_kernel<<<cdiv(HEADS * NTOK * NADLA, 256), 256>>>(na, ha, wa, da, ab);
    // 5) fused attention 1 -> adla_v
    fused_att1<<<dim3(cdiv(NADLA, AT1), BATCH * HEADS), 256>>>(adla, kv, pb, av);
    // 6) fused attention 2 -> attn
    fused_att2<<<dim3(cdiv(NTOK, TM2), BATCH * HEADS), 512, SM2_BYTES>>>(q, adla, av, ab, at);
    // 7) depthwise conv += attn
    dwc_add<<<BATCH * NTOK, DIMC>>>(kv, dwcw, dwcb, at);
    // 8) out = attn @ Wproj + bproj
    sgemm_f2<<<dim3(DIMC / 64, cdiv(MTOT, 128)), 256>>>(at, Wproj, out, bproj, MTOT, DIMC, DIMC);
}

// round 8
// speedup vs baseline: 2.2089x; 1.5407x over previous
#include <cuda_runtime.h>
#include <cuda_bf16.h>
#include <math.h>
#include <stdint.h>
#include <string.h>

#define DIMC   384
#define HEADS  8
#define HD     48
#define NADLA  343
#define HWD    14
#define NTOK   2744
#define BATCH  8
#define MTOT   (BATCH*NTOK)
#define SCALE  0.14433756729740643f

__device__ float g_q   [(long long)MTOT*DIMC];
__device__ float g_kv  [(long long)MTOT*2*DIMC];
__device__ float g_adla[(long long)BATCH*NADLA*DIMC];
__device__ float g_pb  [(long long)HEADS*NADLA*NTOK];
__device__ float g_ab  [(long long)HEADS*NTOK*NADLA];
__device__ float g_adlav[(long long)BATCH*HEADS*NADLA*HD];
__device__ float g_attn[(long long)MTOT*DIMC];

static inline int cdiv(int a, int b) { return (a + b - 1) / b; }

__device__ __forceinline__ void fma2(float2& c, float2 a, float2 b)
{
    unsigned long long cc, aa, bb;
    memcpy(&cc, &c, 8); memcpy(&aa, &a, 8); memcpy(&bb, &b, 8);
    asm("fma.rn.f32x2 %0, %1, %2, %0;" : "+l"(cc) : "l"(aa), "l"(bb));
    memcpy(&c, &cc, 8);
}

// ---------------- dense NN sgemm (f32x2), tile 128x64x16 ----------------
__global__ void __launch_bounds__(256)
sgemm_f2(const float* __restrict__ A, const float* __restrict__ B,
         float* __restrict__ C, const float* __restrict__ bias,
         int M, int N, int K)
{
    __shared__ float As[16][132];
    __shared__ float Bs[16][68];
    const int tid = threadIdx.x, tx = tid & 15, ty = tid >> 4;
    const int row0 = blockIdx.y * 128, col0 = blockIdx.x * 64;

    float2 acc[4][4];
#pragma unroll
    for (int i = 0; i < 4; i++)
#pragma unroll
        for (int j = 0; j < 4; j++) acc[i][j] = make_float2(0.f, 0.f);

    for (int k0 = 0; k0 < K; k0 += 16) {
#pragma unroll
        for (int i = 0; i < 2; i++) {
            int f = tid + i * 256;
            int r = f >> 2, kq = (f & 3) << 2;
            int gr = row0 + r;
            float4 v = make_float4(0.f, 0.f, 0.f, 0.f);
            if (gr < M) v = *(const float4*)(A + (long long)gr * K + k0 + kq);
            As[kq + 0][r] = v.x; As[kq + 1][r] = v.y;
            As[kq + 2][r] = v.z; As[kq + 3][r] = v.w;
        }
        {
            int kk = tid >> 4, nq = (tid & 15) << 2;
            float4 v = *(const float4*)(B + (long long)(k0 + kk) * N + col0 + nq);
            *(float4*)&Bs[kk][nq] = v;
        }
        __syncthreads();
#pragma unroll
        for (int kk = 0; kk < 16; kk++) {
            float2 a2[4];
#pragma unroll
            for (int i = 0; i < 4; i++) a2[i] = *(const float2*)&As[kk][ty * 8 + 2 * i];
            float2 b01 = *(const float2*)&Bs[kk][tx * 4];
            float2 b23 = *(const float2*)&Bs[kk][tx * 4 + 2];
            float2 bb[4] = { make_float2(b01.x, b01.x), make_float2(b01.y, b01.y),
                             make_float2(b23.x, b23.x), make_float2(b23.y, b23.y) };
#pragma unroll
            for (int i = 0; i < 4; i++)
#pragma unroll
                for (int j = 0; j < 4; j++) fma2(acc[i][j], a2[i], bb[j]);
        }
        __syncthreads();
    }
#pragma unroll
    for (int i = 0; i < 4; i++) {
        int gr0 = row0 + ty * 8 + 2 * i, gc = col0 + tx * 4;
        float bx[4] = {0, 0, 0, 0};
        if (bias) {
#pragma unroll
            for (int j = 0; j < 4; j++) bx[j] = bias[gc + j];
        }
        if (gr0 < M)
            *(float4*)(C + (long long)gr0 * N + gc) =
                make_float4(acc[i][0].x + bx[0], acc[i][1].x + bx[1],
                            acc[i][2].x + bx[2], acc[i][3].x + bx[3]);
        if (gr0 + 1 < M)
            *(float4*)(C + (long long)(gr0 + 1) * N + gc) =
                make_float4(acc[i][0].y + bx[0], acc[i][1].y + bx[1],
                            acc[i][2].y + bx[2], acc[i][3].y + bx[3]);
    }
}

// ---------------- fused attention 1: 64 anchors/CTA, 128-token chunks ----------------
#define A1_ATH 0
#define A1_KST 3168            // [48][130]
#define A1_VS  9408            // [128][52]
#define A1_PS  16064           // [64][132]; reused as Osm [64][50]
#define A1_FAC 24512
#define A1_LNV 24576
#define A1_BYTES (24640*4)

__global__ void __launch_bounds__(256, 2) fused_att1(
    const float* __restrict__ adla, const float* __restrict__ kv,
    const float* __restrict__ pb, float* __restrict__ av)
{
    extern __shared__ float sm[];
    float* AthT = sm + A1_ATH;
    float* KsT  = sm + A1_KST;
    float* Vs   = sm + A1_VS;
    float* Ps   = sm + A1_PS;
    float* facs = sm + A1_FAC;
    float* lnv  = sm + A1_LNV;

    const int bh = blockIdx.y, b = bh >> 3, h = bh & 7;
    const int a0blk = blockIdx.x * 64;
    const int tid = threadIdx.x;
    // S mapping
    const int a4 = (tid >> 4) * 4, tg = tid & 15;
    // O mapping
    const int d0 = (tid & 7) * 6, ts = (tid >> 3) & 3, a8 = (tid >> 5) * 8;
    // stage mapping
    const int srow = tid >> 1, scol = (tid & 1) * 24;

    for (int i = tid; i < 64 * 48; i += 256) {
        int a = i / 48, d = i - a * 48;
        int aG = a0blk + a;
        AthT[d * 66 + a] = (aG < NADLA)
            ? adla[((long long)(b * NADLA + aG)) * DIMC + h * HD + d] * SCALE : 0.f;
    }

    const float* pbr[4];
#pragma unroll
    for (int i = 0; i < 4; i++) {
        int aG = a0blk + a4 + i;
        pbr[i] = pb + ((long long)(h * NADLA + (aG < NADLA ? aG : NADLA - 1))) * NTOK;
    }

    float m[4], l[4];
#pragma unroll
    for (int i = 0; i < 4; i++) { m[i] = -INFINITY; l[i] = 0.f; }
    float2 O[8][3];
#pragma unroll
    for (int i = 0; i < 8; i++) O[i][0] = O[i][1] = O[i][2] = make_float2(0.f, 0.f);

    for (int c0 = 0; c0 < NTOK; c0 += 128) {
        {   // stage K^T and V
            int n = c0 + srow;
            bool ok = n < NTOK;
            const float* kb = kv + ((long long)(b * NTOK + (ok ? n : 0))) * 768 + h * HD + scol;
#pragma unroll
            for (int j = 0; j < 24; j += 4) {
                float4 kk = ok ? *(const float4*)(kb + j) : make_float4(0, 0, 0, 0);
                float4 vv = ok ? *(const float4*)(kb + 384 + j) : make_float4(0, 0, 0, 0);
                KsT[(scol + j + 0) * 130 + srow] = kk.x;
                KsT[(scol + j + 1) * 130 + srow] = kk.y;
                KsT[(scol + j + 2) * 130 + srow] = kk.z;
                KsT[(scol + j + 3) * 130 + srow] = kk.w;
                *(float4*)&Vs[srow * 52 + scol + j] = vv;
            }
        }
        __syncthreads();

        // S: thread = 4 anchors x 8 tokens (strided by 16)
        float2 acc[8][2];
#pragma unroll
        for (int j = 0; j < 8; j++) acc[j][0] = acc[j][1] = make_float2(0.f, 0.f);
#pragma unroll 4
        for (int d = 0; d < 48; d++) {
            float2 aL = *(const float2*)&AthT[d * 66 + a4];
            float2 aH = *(const float2*)&AthT[d * 66 + a4 + 2];
            const float* kr = &KsT[d * 130 + tg];
#pragma unroll
            for (int j = 0; j < 8; j++) {
                float kx = kr[16 * j];
                float2 kk = make_float2(kx, kx);
                fma2(acc[j][0], aL, kk);
                fma2(acc[j][1], aH, kk);
            }
        }
#pragma unroll
        for (int i = 0; i < 4; i++) {
            float s[8];
            float mx = -INFINITY;
#pragma unroll
            for (int j = 0; j < 8; j++) {
                int n = c0 + tg + 16 * j;
                float sv = (i & 1) ? acc[j][i >> 1].y : acc[j][i >> 1].x;
                s[j] = (n < NTOK) ? sv + pbr[i][n] : -INFINITY;
                mx = fmaxf(mx, s[j]);
            }
#pragma unroll
            for (int o = 1; o < 16; o <<= 1)
                mx = fmaxf(mx, __shfl_xor_sync(0xffffffffu, mx, o));
            float mn = fmaxf(m[i], mx);
            float sum = 0.f;
#pragma unroll
            for (int j = 0; j < 8; j++) {
                float pv = __expf(s[j] - mn);
                Ps[(a4 + i) * 132 + tg + 16 * j] = pv;
                sum += pv;
            }
#pragma unroll
            for (int o = 1; o < 16; o <<= 1)
                sum += __shfl_xor_sync(0xffffffffu, sum, o);
            float fac = __expf(m[i] - mn);
            l[i] = l[i] * fac + sum;
            m[i] = mn;
            if (tg == 0) facs[a4 + i] = fac;
        }
        __syncthreads();

        // O: thread = 8 anchors x 6 dims, token-quarter ts
        {
#pragma unroll
            for (int i = 0; i < 8; i++) {
                float f = facs[a8 + i];
                O[i][0].x *= f; O[i][0].y *= f;
                O[i][1].x *= f; O[i][1].y *= f;
                O[i][2].x *= f; O[i][2].y *= f;
            }
#pragma unroll 2
            for (int jj = 0; jj < 32; jj++) {
                int j = 4 * jj + ts;
                const float* vr = &Vs[j * 52 + d0];
                float2 v0 = *(const float2*)(vr);
                float2 v1 = *(const float2*)(vr + 2);
                float2 v2 = *(const float2*)(vr + 4);
#pragma unroll
                for (int i = 0; i < 8; i++) {
                    float p = Ps[(a8 + i) * 132 + j];
                    float2 pp = make_float2(p, p);
                    fma2(O[i][0], pp, v0);
                    fma2(O[i][1], pp, v1);
                    fma2(O[i][2], pp, v2);
                }
            }
        }
        __syncthreads();
    }

    if (tg == 0) {
#pragma unroll
        for (int i = 0; i < 4; i++) lnv[a4 + i] = 1.f / l[i];
    }
    float* Osm = Ps;  // [64][50]
    if (ts == 0) {
#pragma unroll
        for (int i = 0; i < 8; i++) {
            float* dst = &Osm[(a8 + i) * 50 + d0];
            *(float2*)(dst) = O[i][0]; *(float2*)(dst + 2) = O[i][1]; *(float2*)(dst + 4) = O[i][2];
        }
    }
    __syncthreads();
#pragma unroll
    for (int k = 1; k < 4; k++) {
        if (ts == k) {
#pragma unroll
            for (int i = 0; i < 8; i++) {
                float* dst = &Osm[(a8 + i) * 50 + d0];
                float2 t0 = *(float2*)(dst), t1 = *(float2*)(dst + 2), t2 = *(float2*)(dst + 4);
                t0.x += O[i][0].x; t0.y += O[i][0].y;
                t1.x += O[i][1].x; t1.y += O[i][1].y;
                t2.x += O[i][2].x; t2.y += O[i][2].y;
                *(float2*)(dst) = t0; *(float2*)(dst + 2) = t1; *(float2*)(dst + 4) = t2;
            }
        }
        __syncthreads();
    }
    for (int i = tid; i < 64 * 48; i += 256) {
        int a = i / 48, d = i - a * 48;
        int aG = a0blk + a;
        if (aG < NADLA)
            av[((long long)bh * NADLA + aG) * HD + d] = Osm[a * 50 + d] * lnv[a];
    }
}

// ---------------- fused attention 2: 64 rows/CTA, anchors resident ----------------
#define A2_U   0               // AthT[48][352] then V[343][52]
#define A2_LS  17900           // Ls[64][360]
#define A2_QS  40940           // qT[48][66] then Osm[64][50]
#define A2_LNV 44140
#define A2_BYTES (44204*4)

__global__ void __launch_bounds__(512, 1) fused_att2(
    const float* __restrict__ q, const float* __restrict__ adla,
    const float* __restrict__ av, const float* __restrict__ ab,
    float* __restrict__ attn)
{
    extern __shared__ float sm[];
    float* U   = sm + A2_U;
    float* Ls  = sm + A2_LS;
    float* QS  = sm + A2_QS;
    float* lnv = sm + A2_LNV;

    const int bh = blockIdx.y, b = bh >> 3, h = bh & 7;
    const int n0 = blockIdx.x * 64;
    const int tid = threadIdx.x;

    for (int i = tid; i < 48 * 352; i += 512) {
        int d = i / 352, a = i - d * 352;
        U[i] = (a < NADLA) ? adla[((long long)(b * NADLA + a)) * DIMC + h * HD + d] : 0.f;
    }
    for (int i = tid; i < 64 * 48; i += 512) {
        int r = i / 48, d = i - r * 48;
        int n = n0 + r; int nC = n < NTOK ? n : NTOK - 1;
        QS[d * 66 + r] = q[((long long)(b * NTOK + nC)) * DIMC + h * HD + d] * SCALE;
    }
    __syncthreads();

    // phase A: thread = 4 rows x 22 anchors, 2-way d-split
    {
        const int dsel = tid >> 8, rem = tid & 255;
        const int r0 = (rem >> 4) * 4, a0 = (rem & 15) * 22;
        float2 acc[4][11];
#pragma unroll
        for (int i = 0; i < 4; i++)
#pragma unroll
            for (int j = 0; j < 11; j++) acc[i][j] = make_float2(0.f, 0.f);
        const int dbase = dsel * 24;
#pragma unroll 2
        for (int dd = 0; dd < 24; dd++) {
            int d = dbase + dd;
            float2 q01 = *(const float2*)&QS[d * 66 + r0];
            float2 q23 = *(const float2*)&QS[d * 66 + r0 + 2];
            float2 Q0 = make_float2(q01.x, q01.x), Q1 = make_float2(q01.y, q01.y);
            float2 Q2 = make_float2(q23.x, q23.x), Q3 = make_float2(q23.y, q23.y);
            const float* ar = &U[d * 352 + a0];
#pragma unroll
            for (int j = 0; j < 11; j++) {
                float2 Ar = *(const float2*)(ar + 2 * j);
                fma2(acc[0][j], Q0, Ar); fma2(acc[1][j], Q1, Ar);
                fma2(acc[2][j], Q2, Ar); fma2(acc[3][j], Q3, Ar);
            }
        }
        if (dsel == 0) {
#pragma unroll
            for (int i = 0; i < 4; i++) {
                int n = n0 + r0 + i; int nC = n < NTOK ? n : NTOK - 1;
                const float* abr = ab + ((long long)(h * NTOK + nC)) * NADLA;
#pragma unroll
                for (int j = 0; j < 11; j++) {
                    int a = a0 + 2 * j;
                    if (a < NADLA)     Ls[(r0 + i) * 360 + a]     = acc[i][j].x + abr[a];
                    if (a + 1 < NADLA) Ls[(r0 + i) * 360 + a + 1] = acc[i][j].y + abr[a + 1];
                }
            }
        }
        __syncthreads();
        if (dsel == 1) {
#pragma unroll
            for (int i = 0; i < 4; i++)
#pragma unroll
                for (int j = 0; j < 11; j++) {
                    int a = a0 + 2 * j;
                    if (a < NADLA)     Ls[(r0 + i) * 360 + a]     += acc[i][j].x;
                    if (a + 1 < NADLA) Ls[(r0 + i) * 360 + a + 1] += acc[i][j].y;
                }
        }
        __syncthreads();
    }

    // stage V into U (AthT dead) + phase B softmax
    for (int i = tid; i < NADLA * 48; i += 512) {
        int a = i / 48, c = i - a * 48;
        U[a * 52 + c] = av[((long long)bh * NADLA + a) * HD + c];
    }
    {
        const int r = tid >> 3, t8 = tid & 7;
        float mx = -INFINITY;
        for (int a = t8; a < NADLA; a += 8) mx = fmaxf(mx, Ls[r * 360 + a]);
#pragma unroll
        for (int o = 1; o < 8; o <<= 1)
            mx = fmaxf(mx, __shfl_xor_sync(0xffffffffu, mx, o));
        float sum = 0.f;
        for (int a = t8; a < NADLA; a += 8) {
            float pv = __expf(Ls[r * 360 + a] - mx);
            Ls[r * 360 + a] = pv;
            sum += pv;
        }
#pragma unroll
        for (int o = 1; o < 8; o <<= 1)
            sum += __shfl_xor_sync(0xffffffffu, sum, o);
        if (t8 == 0) lnv[r] = 1.f / sum;
    }
    __syncthreads();

    // phase C: thread = 8 rows x 6 dims, anchor-eighth
    {
        const int d0 = (tid & 7) * 6;
        const int as = (tid >> 3) & 7;
        const int r0 = (tid >> 6) * 8;
        float2 acc[8][3];
#pragma unroll
        for (int i = 0; i < 8; i++) acc[i][0] = acc[i][1] = acc[i][2] = make_float2(0.f, 0.f);
        for (int a = as; a < NADLA; a += 8) {
            const float* vr = &U[a * 52 + d0];
            float2 v0 = *(const float2*)(vr);
            float2 v1 = *(const float2*)(vr + 2);
            float2 v2 = *(const float2*)(vr + 4);
#pragma unroll
            for (int i = 0; i < 8; i++) {
                float pv = Ls[(r0 + i) * 360 + a];
                float2 pp = make_float2(pv, pv);
                fma2(acc[i][0], pp, v0); fma2(acc[i][1], pp, v1); fma2(acc[i][2], pp, v2);
            }
        }
        __syncthreads();
        float* Osm = QS;  // [64][50]
        if (as == 0) {
#pragma unroll
            for (int i = 0; i < 8; i++) {
                float* dst = &Osm[(r0 + i) * 50 + d0];
                *(float2*)(dst) = acc[i][0]; *(float2*)(dst + 2) = acc[i][1]; *(float2*)(dst + 4) = acc[i][2];
            }
        }
        __syncthreads();
#pragma unroll
        for (int k = 1; k < 8; k++) {
            if (as == k) {
#pragma unroll
                for (int i = 0; i < 8; i++) {
                    float* dst = &Osm[(r0 + i) * 50 + d0];
                    float2 t0 = *(float2*)(dst), t1 = *(float2*)(dst + 2), t2 = *(float2*)(dst + 4);
                    t0.x += acc[i][0].x; t0.y += acc[i][0].y;
                    t1.x += acc[i][1].x; t1.y += acc[i][1].y;
                    t2.x += acc[i][2].x; t2.y += acc[i][2].y;
                    *(float2*)(dst) = t0; *(float2*)(dst + 2) = t1; *(float2*)(dst + 4) = t2;
                }
            }
            __syncthreads();
        }
    }
    for (int i = tid; i < 64 * 48; i += 512) {
        int r = i / 48, d = i - r * 48;
        int n = n0 + r;
        if (n < NTOK)
            attn[((long long)(b * NTOK + n)) * DIMC + h * HD + d] = QS[r * 50 + d] * lnv[r];
    }
}

// ---------------- pooling ----------------
__global__ void pool_adla(const float* __restrict__ q, float* __restrict__ adla)
{
    int idx = blockIdx.x * 256 + threadIdx.x;
    if (idx >= BATCH * NADLA * DIMC) return;
    int c = idx % DIMC;
    int a = (idx / DIMC) % NADLA;
    int b = idx / (DIMC * NADLA);
    int a1 = a / 49, a2 = (a / 7) % 7, a3 = a % 7;
    float s = 0.f;
#pragma unroll
    for (int i = 0; i < 2; i++)
#pragma unroll
        for (int j = 0; j < 2; j++)
#pragma unroll
            for (int k = 0; k < 2; k++) {
                int n = ((2 * a1 + i) * HWD + (2 * a2 + j)) * HWD + (2 * a3 + k);
                s += q[((long long)(b * NTOK + n)) * DIMC + c];
            }
    adla[idx] = s * 0.125f;
}

// ---------------- bias tables ----------------
__device__ __forceinline__ void lin_w(int o, int& i0, int& i1, float& w)
{
    float x = 0.5f * o - 0.25f;
    x = fminf(fmaxf(x, 0.f), 6.f);
    i0 = (int)floorf(x);
    i1 = min(i0 + 1, 6);
    w = x - (float)i0;
}

__device__ __forceinline__ float interp3(const float* base, int x, int y, int z)
{
    int x0, x1, y0, y1, z0, z1;
    float wx, wy, wz;
    lin_w(x, x0, x1, wx); lin_w(y, y0, y1, wy); lin_w(z, z0, z1, wz);
    float c000 = base[x0 * 49 + y0 * 7 + z0], c001 = base[x0 * 49 + y0 * 7 + z1];
    float c010 = base[x0 * 49 + y1 * 7 + z0], c011 = base[x0 * 49 + y1 * 7 + z1];
    float c100 = base[x1 * 49 + y0 * 7 + z0], c101 = base[x1 * 49 + y0 * 7 + z1];
    float c110 = base[x1 * 49 + y1 * 7 + z0], c111 = base[x1 * 49 + y1 * 7 + z1];
    float v0 = (1.f - wy) * ((1.f - wz) * c000 + wz * c001) + wy * ((1.f - wz) * c010 + wz * c011);
    float v1 = (1.f - wy) * ((1.f - wz) * c100 + wz * c101) + wy * ((1.f - wz) * c110 + wz * c111);
    return (1.f - wx) * v0 + wx * v1;
}

__global__ void pb_kernel(const float* __restrict__ an, const float* __restrict__ ah,
                          const float* __restrict__ aw, const float* __restrict__ ad,
                          float* __restrict__ pb)
{
    int idx = blockIdx.x * 256 + threadIdx.x;
    if (idx >= HEADS * NADLA * NTOK) return;
    int n = idx % NTOK;
    int a = (idx / NTOK) % NADLA;
    int h = idx / (NTOK * NADLA);
    int x = n / 196, y = (n / 14) % 14, z = n % 14;
    const float* base = an + ((long long)(h * NADLA + a)) * NADLA;
    float v = interp3(base, x, y, z);
    v += ah[(h * NADLA + a) * HWD + x];
    v += aw[(h * NADLA + a) * HWD + y];
    v += ad[(h * NADLA + a) * HWD + z];
    pb[idx] = v;
}

__global__ void ab_kernel(const float* __restrict__ na, const float* __restrict__ ha,
                          const float* __restrict__ wa, const float* __restrict__ da,
                          float* __restrict__ ab)
{
    int idx = blockIdx.x * 256 + threadIdx.x;
    if (idx >= HEADS * NTOK * NADLA) return;
    int a = idx % NADLA;
    int n = (idx / NADLA) % NTOK;
    int h = idx / (NADLA * NTOK);
    int x = n / 196, y = (n / 14) % 14, z = n % 14;
    const float* base = na + ((long long)(h * NADLA + a)) * NADLA;
    float v = interp3(base, x, y, z);
    v += ha[(h * HWD + x) * NADLA + a];
    v += wa[(h * HWD + y) * NADLA + a];
    v += da[(h * HWD + z) * NADLA + a];
    ab[idx] = v;
}

// ---------------- depthwise 3x3x3 conv, += into attn ----------------
__global__ void dwc_add(const float* __restrict__ kv, const float* __restrict__ w,
                        const float* __restrict__ bias, float* __restrict__ attn)
{
    int blk = blockIdx.x;
    int c = threadIdx.x;
    int b = blk / NTOK, n = blk % NTOK;
    int x = n / 196, y = (n / 14) % 14, z = n % 14;
    float acc = bias[c];
    const float* wc = w + c * 27;
#pragma unroll
    for (int i = -1; i <= 1; i++) {
        int xx = x + i;
        if ((unsigned)xx >= (unsigned)HWD) continue;
#pragma unroll
        for (int j = -1; j <= 1; j++) {
            int yy = y + j;
            if ((unsigned)yy >= (unsigned)HWD) continue;
#pragma unroll
            for (int k = -1; k <= 1; k++) {
                int zz = z + k;
                if ((unsigned)zz >= (unsigned)HWD) continue;
                int nn = (xx * HWD + yy) * HWD + zz;
                acc = fmaf(kv[((long long)(b * NTOK + nn)) * 768 + DIMC + c],
                           wc[(i + 1) * 9 + (j + 1) * 3 + (k + 1)], acc);
            }
        }
    }
    attn[(long long)blk * DIMC + c] += acc;
}

// ---------------- launcher ----------------
extern "C" void kernel_launch(void* const* d_in, const int* in_sizes, int n_in,
                              void* d_out, int out_size)
{
    const float* x     = (const float*)d_in[0];
    const float* Wq    = (const float*)d_in[1];
    const float* Wkv   = (const float*)d_in[2];
    const float* Wproj = (const float*)d_in[3];
    const float* bproj = (const float*)d_in[4];
    const float* dwcw  = (const float*)d_in[5];
    const float* dwcb  = (const float*)d_in[6];
    const float* an    = (const float*)d_in[7];
    const float* na    = (const float*)d_in[8];
    const float* ah    = (const float*)d_in[9];
    const float* aw    = (const float*)d_in[10];
    const float* ad    = (const float*)d_in[11];
    const float* ha    = (const float*)d_in[12];
    const float* wa    = (const float*)d_in[13];
    const float* da    = (const float*)d_in[14];
    float* out = (float*)d_out;

    void* p;
    cudaGetSymbolAddress(&p, g_q);     float* q    = (float*)p;
    cudaGetSymbolAddress(&p, g_kv);    float* kv   = (float*)p;
    cudaGetSymbolAddress(&p, g_adla);  float* adla = (float*)p;
    cudaGetSymbolAddress(&p, g_pb);    float* pb   = (float*)p;
    cudaGetSymbolAddress(&p, g_ab);    float* ab   = (float*)p;
    cudaGetSymbolAddress(&p, g_adlav); float* av   = (float*)p;
    cudaGetSymbolAddress(&p, g_attn);  float* at   = (float*)p;

    cudaFuncSetAttribute(fused_att1, cudaFuncAttributeMaxDynamicSharedMemorySize, A1_BYTES);
    cudaFuncSetAttribute(fused_att2, cudaFuncAttributeMaxDynamicSharedMemorySize, A2_BYTES);

    sgemm_f2<<<dim3(DIMC / 64, cdiv(MTOT, 128)), 256>>>(x, Wq, q, nullptr, MTOT, DIMC, DIMC);
    sgemm_f2<<<dim3(768 / 64, cdiv(MTOT, 128)), 256>>>(x, Wkv, kv, nullptr, MTOT, 768, DIMC);
    pool_adla<<<cdiv(BATCH * NADLA * DIMC, 256), 256>>>(q, adla);
    pb_kernel<<<cdiv(HEADS * NADLA * NTOK, 256), 256>>>(an, ah, aw, ad, pb);
    ab_kernel<<<cdiv(HEADS * NTOK * NADLA, 256), 256>>>(na, ha, wa, da, ab);
    fused_att1<<<dim3(cdiv(NADLA, 64), BATCH * HEADS), 256, A1_BYTES>>>(adla, kv, pb, av);
    fused_att2<<<dim3(cdiv(NTOK, 64), BATCH * HEADS), 512, A2_BYTES>>>(q, adla, av, ab, at);
    dwc_add<<<BATCH * NTOK, DIMC>>>(kv, dwcw, dwcb, at);
    sgemm_f2<<<dim3(DIMC / 64, cdiv(MTOT, 128)), 256>>>(at, Wproj, out, bproj, MTOT, DIMC, DIMC);
}